// round 1
// baseline (speedup 1.0000x reference)
#include <cuda_runtime.h>
#include <math.h>

// Problem constants (fixed by setup_inputs)
#define BT   8192   // B*T
#define EDIM 512    // E
#define G4   2048   // 4*E
#define NK   1024   // N*K_SUP
#define NBAT 64     // B
#define TQ   128    // T
#define STEPS 10

// Scratch (device globals: allocation-free rule)
__device__ float g_xw[(long)BT * G4];      // x@W_ih^T + b  (precomputed, reused every step)
__device__ float g_gates[(long)BT * G4];
__device__ float g_h[(long)BT * EDIM];
__device__ float g_c[(long)BT * EDIM];
__device__ float g_scores[(long)BT * NK];  // scores -> attn (in-place softmax)
__device__ float g_r[(long)BT * EDIM];

__device__ __forceinline__ float sigf(float x) { return 1.f / (1.f + __expf(-x)); }

// ---------------------------------------------------------------------------
// NT GEMM: C[m,n] = sum_k A[m,k]*B[n,k]  (+ Cadd[m,n]) (+ bias1[n]+bias2[n])
// A: MxK row-major, B: NxK row-major. 128x128x16 tile, 256 threads, 8x8/thread.
// All dims assumed multiples of tile sizes (true for this problem).
// ---------------------------------------------------------------------------
template <bool ADD_C, bool ADD_BIAS>
__global__ __launch_bounds__(256) void gemm_nt(
    const float* __restrict__ A, const float* __restrict__ B,
    const float* __restrict__ Cadd,
    const float* __restrict__ bias1, const float* __restrict__ bias2,
    float* __restrict__ C,
    int M, int N, int K,
    long sA, long sB, long sC)
{
    constexpr int BM = 128, BN = 128, BK = 16;
    __shared__ float As[BK][BM];
    __shared__ float Bs[BK][BN];

    A += (long)blockIdx.z * sA;
    B += (long)blockIdx.z * sB;
    C += (long)blockIdx.z * sC;
    if (ADD_C) Cadd += (long)blockIdx.z * sC;

    const int bm = blockIdx.y * BM;
    const int bn = blockIdx.x * BN;
    const int tid = threadIdx.x;
    const int lrow = tid >> 2;          // 0..63
    const int lcol = (tid & 3) << 2;    // 0,4,8,12
    const int tx = tid & 15, ty = tid >> 4;

    float acc[8][8] = {};

    for (int k0 = 0; k0 < K; k0 += BK) {
#pragma unroll
        for (int i = 0; i < 2; i++) {
            int r = lrow + i * 64;
            float4 va = *(const float4*)&A[(long)(bm + r) * K + k0 + lcol];
            As[lcol + 0][r] = va.x; As[lcol + 1][r] = va.y;
            As[lcol + 2][r] = va.z; As[lcol + 3][r] = va.w;
            float4 vb = *(const float4*)&B[(long)(bn + r) * K + k0 + lcol];
            Bs[lcol + 0][r] = vb.x; Bs[lcol + 1][r] = vb.y;
            Bs[lcol + 2][r] = vb.z; Bs[lcol + 3][r] = vb.w;
        }
        __syncthreads();
#pragma unroll
        for (int k = 0; k < BK; k++) {
            float4 a0 = *(const float4*)&As[k][ty * 8];
            float4 a1 = *(const float4*)&As[k][ty * 8 + 4];
            float4 b0 = *(const float4*)&Bs[k][tx * 8];
            float4 b1 = *(const float4*)&Bs[k][tx * 8 + 4];
            float a[8] = {a0.x, a0.y, a0.z, a0.w, a1.x, a1.y, a1.z, a1.w};
            float b[8] = {b0.x, b0.y, b0.z, b0.w, b1.x, b1.y, b1.z, b1.w};
#pragma unroll
            for (int i = 0; i < 8; i++)
#pragma unroll
                for (int j = 0; j < 8; j++)
                    acc[i][j] = fmaf(a[i], b[j], acc[i][j]);
        }
        __syncthreads();
    }

#pragma unroll
    for (int i = 0; i < 8; i++) {
        int m = bm + ty * 8 + i;
#pragma unroll
        for (int jj = 0; jj < 2; jj++) {
            int n = bn + tx * 8 + jj * 4;
            float4 v = make_float4(acc[i][jj * 4 + 0], acc[i][jj * 4 + 1],
                                   acc[i][jj * 4 + 2], acc[i][jj * 4 + 3]);
            if (ADD_C) {
                float4 cv = *(const float4*)&Cadd[(long)m * N + n];
                v.x += cv.x; v.y += cv.y; v.z += cv.z; v.w += cv.w;
            }
            if (ADD_BIAS) {
                v.x += bias1[n + 0] + bias2[n + 0];
                v.y += bias1[n + 1] + bias2[n + 1];
                v.z += bias1[n + 2] + bias2[n + 2];
                v.w += bias1[n + 3] + bias2[n + 3];
            }
            *(float4*)&C[(long)m * N + n] = v;
        }
    }
}

// ---------------------------------------------------------------------------
// NN GEMM: C[m,n] = sum_k A[m,k]*B[k,n].  A: MxK row-major, B: KxN row-major.
// ---------------------------------------------------------------------------
__global__ __launch_bounds__(256) void gemm_nn(
    const float* __restrict__ A, const float* __restrict__ B,
    float* __restrict__ C,
    int M, int N, int K,
    long sA, long sB, long sC)
{
    constexpr int BM = 128, BN = 128, BK = 16;
    __shared__ float As[BK][BM];
    __shared__ float Bs[BK][BN];

    A += (long)blockIdx.z * sA;
    B += (long)blockIdx.z * sB;
    C += (long)blockIdx.z * sC;

    const int bm = blockIdx.y * BM;
    const int bn = blockIdx.x * BN;
    const int tid = threadIdx.x;
    const int larow = tid >> 2;         // 0..63
    const int lacol = (tid & 3) << 2;   // 0,4,8,12
    const int lbrow = tid >> 5;         // 0..7
    const int lbcol = (tid & 31) << 2;  // 0..124
    const int tx = tid & 15, ty = tid >> 4;

    float acc[8][8] = {};

    for (int k0 = 0; k0 < K; k0 += BK) {
#pragma unroll
        for (int i = 0; i < 2; i++) {
            int r = larow + i * 64;
            float4 va = *(const float4*)&A[(long)(bm + r) * K + k0 + lacol];
            As[lacol + 0][r] = va.x; As[lacol + 1][r] = va.y;
            As[lacol + 2][r] = va.z; As[lacol + 3][r] = va.w;
            int br = lbrow + i * 8;
            float4 vb = *(const float4*)&B[(long)(k0 + br) * N + bn + lbcol];
            *(float4*)&Bs[br][lbcol] = vb;
        }
        __syncthreads();
#pragma unroll
        for (int k = 0; k < BK; k++) {
            float4 a0 = *(const float4*)&As[k][ty * 8];
            float4 a1 = *(const float4*)&As[k][ty * 8 + 4];
            float4 b0 = *(const float4*)&Bs[k][tx * 8];
            float4 b1 = *(const float4*)&Bs[k][tx * 8 + 4];
            float a[8] = {a0.x, a0.y, a0.z, a0.w, a1.x, a1.y, a1.z, a1.w};
            float b[8] = {b0.x, b0.y, b0.z, b0.w, b1.x, b1.y, b1.z, b1.w};
#pragma unroll
            for (int i = 0; i < 8; i++)
#pragma unroll
                for (int j = 0; j < 8; j++)
                    acc[i][j] = fmaf(a[i], b[j], acc[i][j]);
        }
        __syncthreads();
    }

#pragma unroll
    for (int i = 0; i < 8; i++) {
        int m = bm + ty * 8 + i;
#pragma unroll
        for (int jj = 0; jj < 2; jj++) {
            int n = bn + tx * 8 + jj * 4;
            float4 v = make_float4(acc[i][jj * 4 + 0], acc[i][jj * 4 + 1],
                                   acc[i][jj * 4 + 2], acc[i][jj * 4 + 3]);
            *(float4*)&C[(long)m * N + n] = v;
        }
    }
}

// ---------------------------------------------------------------------------
// Row softmax over NK=1024 columns, in place. One block (256 thr) per row.
// ---------------------------------------------------------------------------
__device__ __forceinline__ float warp_max(float v) {
#pragma unroll
    for (int o = 16; o; o >>= 1) v = fmaxf(v, __shfl_xor_sync(0xFFFFFFFFu, v, o));
    return v;
}
__device__ __forceinline__ float warp_sum(float v) {
#pragma unroll
    for (int o = 16; o; o >>= 1) v += __shfl_xor_sync(0xFFFFFFFFu, v, o);
    return v;
}

__global__ __launch_bounds__(256) void softmax_rows(float* __restrict__ S)
{
    __shared__ float shm[8];
    __shared__ float shs[8];
    const long row = blockIdx.x;
    float4* p = (float4*)(S + row * (long)NK);
    const int tid = threadIdx.x;

    float4 v = p[tid];
    float m = fmaxf(fmaxf(v.x, v.y), fmaxf(v.z, v.w));
    m = warp_max(m);
    if ((tid & 31) == 0) shm[tid >> 5] = m;
    __syncthreads();
    if (tid < 32) {
        float t = (tid < 8) ? shm[tid] : -3.402823466e38f;
        t = warp_max(t);
        if (tid == 0) shm[0] = t;
    }
    __syncthreads();
    m = shm[0];

    float ex = __expf(v.x - m), ey = __expf(v.y - m);
    float ez = __expf(v.z - m), ew = __expf(v.w - m);
    float s = (ex + ey) + (ez + ew);
    s = warp_sum(s);
    if ((tid & 31) == 0) shs[tid >> 5] = s;
    __syncthreads();
    if (tid < 32) {
        float t = (tid < 8) ? shs[tid] : 0.f;
        t = warp_sum(t);
        if (tid == 0) shs[0] = t;
    }
    __syncthreads();
    float inv = 1.f / shs[0];
    p[tid] = make_float4(ex * inv, ey * inv, ez * inv, ew * inv);
}

// ---------------------------------------------------------------------------
// LSTM pointwise: c_new = sig(f)*c + sig(i)*tanh(g);
//                 h_new = sig(o)*tanh(c_new) + x + r
// ---------------------------------------------------------------------------
__global__ __launch_bounds__(256) void lstm_pointwise(
    const float* __restrict__ gates, const float* __restrict__ x,
    const float* __restrict__ r, float* __restrict__ h_out,
    float* __restrict__ c)
{
    long idx = (long)blockIdx.x * blockDim.x + threadIdx.x;  // < BT*EDIM
    int m = (int)(idx >> 9);         // /EDIM
    int e = (int)(idx & (EDIM - 1));
    const float* g = gates + (long)m * G4;
    float gi = g[e], gf = g[EDIM + e], gg = g[2 * EDIM + e], go = g[3 * EDIM + e];
    float cn = sigf(gf) * c[idx] + sigf(gi) * tanhf(gg);
    float hn = sigf(go) * tanhf(cn) + x[idx] + r[idx];
    c[idx] = cn;
    h_out[idx] = hn;
}

__global__ void zero2(float* __restrict__ a, float* __restrict__ b)
{
    long i = (long)blockIdx.x * blockDim.x + threadIdx.x;
    a[i] = 0.f;
    b[i] = 0.f;
}

// ---------------------------------------------------------------------------
extern "C" void kernel_launch(void* const* d_in, const int* in_sizes, int n_in,
                              void* d_out, int out_size)
{
    const float* targets = (const float*)d_in[0];  // (B,T,E) -> (8192,512)
    const float* sup     = (const float*)d_in[1];  // (B,N,K,E) -> (64,1024,512)
    const float* W_ih    = (const float*)d_in[2];  // (2048,512)
    const float* W_hh    = (const float*)d_in[3];  // (2048,512)
    const float* b_ih    = (const float*)d_in[4];  // (2048)
    const float* b_hh    = (const float*)d_in[5];  // (2048)
    float* out = (float*)d_out;

    float *xw, *gates, *h, *c, *scores, *r;
    cudaGetSymbolAddress((void**)&xw, g_xw);
    cudaGetSymbolAddress((void**)&gates, g_gates);
    cudaGetSymbolAddress((void**)&h, g_h);
    cudaGetSymbolAddress((void**)&c, g_c);
    cudaGetSymbolAddress((void**)&scores, g_scores);
    cudaGetSymbolAddress((void**)&r, g_r);

    // h0 = c0 = 0
    zero2<<<(BT * EDIM) / 256, 256>>>(h, c);

    // xW = targets @ W_ih^T + b_ih + b_hh   (step-invariant)
    gemm_nt<false, true><<<dim3(G4 / 128, BT / 128, 1), 256>>>(
        targets, W_ih, nullptr, b_ih, b_hh, xw, BT, G4, EDIM, 0, 0, 0);

    for (int s = 0; s < STEPS; s++) {
        // gates = xW + h_prev @ W_hh^T
        gemm_nt<true, false><<<dim3(G4 / 128, BT / 128, 1), 256>>>(
            h, W_hh, xw, nullptr, nullptr, gates, BT, G4, EDIM, 0, 0, 0);

        // scores[b,t,p] = h_prev[b,t,:] . sup[b,p,:]   (batched over b)
        gemm_nt<false, false><<<dim3(NK / 128, TQ / 128, NBAT), 256>>>(
            h, sup, nullptr, nullptr, nullptr, scores,
            TQ, NK, EDIM, (long)TQ * EDIM, (long)NK * EDIM, (long)TQ * NK);

        // softmax over NK
        softmax_rows<<<BT, 256>>>(scores);

        // r[b,t,:] = attn[b,t,:] @ sup[b,:,:]   (batched over b)
        gemm_nn<<<dim3(EDIM / 128, TQ / 128, NBAT), 256>>>(
            scores, sup, r,
            TQ, EDIM, NK, (long)TQ * NK, (long)NK * EDIM, (long)TQ * EDIM);

        // h,c update (last step writes straight to d_out)
        float* hdst = (s == STEPS - 1) ? out : h;
        lstm_pointwise<<<(BT * EDIM) / 256, 256>>>(gates, targets, r, hdst, c);
    }
}

// round 4
// speedup vs baseline: 2.9887x; 2.9887x over previous
#include <cuda_runtime.h>
#include <cuda_bf16.h>
#include <cstdint>
#include <math.h>

// ---------------- problem constants ----------------
#define BT    8192   // B*T
#define EDIM  512
#define G4    2048   // 4*E
#define NKDIM 1024   // N*K_SUP
#define NBAT  64
#define TQ    128
#define STEPS 10

// ---------------- GEMM tile config ----------------
#define BM 128
#define BN 128
#define BK 32
#define STAGE_BYTES 32768u   // Ah 8K + Al 8K + Bh 8K + Bl 8K
#define DYN_SMEM    65536    // 2 stages

// ---------------- device scratch ----------------
__device__ float g_xw[(long)BT * G4];
__device__ float g_gates[(long)BT * G4];
__device__ float g_scores[(long)BT * NKDIM];
__device__ float g_r[(long)BT * EDIM];
__device__ float g_c[(long)BT * EDIM];
__device__ __nv_bfloat16 g_h_hi[(long)BT * EDIM];
__device__ __nv_bfloat16 g_h_lo[(long)BT * EDIM];
__device__ __nv_bfloat16 g_tg_hi[(long)BT * EDIM];
__device__ __nv_bfloat16 g_tg_lo[(long)BT * EDIM];
__device__ __nv_bfloat16 g_wih_hi[(long)G4 * EDIM];
__device__ __nv_bfloat16 g_wih_lo[(long)G4 * EDIM];
__device__ __nv_bfloat16 g_whh_hi[(long)G4 * EDIM];
__device__ __nv_bfloat16 g_whh_lo[(long)G4 * EDIM];
__device__ __nv_bfloat16 g_sup_hi[(long)NBAT * NKDIM * EDIM];
__device__ __nv_bfloat16 g_sup_lo[(long)NBAT * NKDIM * EDIM];
__device__ __nv_bfloat16 g_supT_hi[(long)NBAT * EDIM * NKDIM];
__device__ __nv_bfloat16 g_supT_lo[(long)NBAT * EDIM * NKDIM];
__device__ __nv_bfloat16 g_attn_hi[(long)BT * NKDIM];
__device__ __nv_bfloat16 g_attn_lo[(long)BT * NKDIM];

// ---------------- helpers ----------------
__device__ __forceinline__ uint32_t smem_u32(const void* p) {
    uint32_t a;
    asm("{ .reg .u64 t; cvta.to.shared.u64 t, %1; cvt.u32.u64 %0, t; }" : "=r"(a) : "l"(p));
    return a;
}
__device__ __forceinline__ void cp16(uint32_t dst, const void* src) {
    asm volatile("cp.async.cg.shared.global [%0], [%1], 16;" :: "r"(dst), "l"(src));
}
__device__ __forceinline__ uint32_t sw64(uint32_t x) { return x ^ ((x >> 3) & 0x30u); }

__device__ __forceinline__ void ldm4(uint32_t* r, uint32_t addr) {
    asm volatile("ldmatrix.sync.aligned.m8n8.x4.shared.b16 {%0,%1,%2,%3}, [%4];"
                 : "=r"(r[0]), "=r"(r[1]), "=r"(r[2]), "=r"(r[3]) : "r"(addr));
}
__device__ __forceinline__ void mma16816(float* c, const uint32_t* a, const uint32_t* b) {
    asm volatile(
        "mma.sync.aligned.m16n8k16.row.col.f32.bf16.bf16.f32 "
        "{%0,%1,%2,%3}, {%4,%5,%6,%7}, {%8,%9}, {%0,%1,%2,%3};"
        : "+f"(c[0]), "+f"(c[1]), "+f"(c[2]), "+f"(c[3])
        : "r"(a[0]), "r"(a[1]), "r"(a[2]), "r"(a[3]), "r"(b[0]), "r"(b[1]));
}

__device__ __forceinline__ float sigf(float x) { return 1.f / (1.f + __expf(-x)); }

// ---------------------------------------------------------------------------
// bf16x3 split GEMM (NT): C = A*B^T with A=(Ah+Al), B=(Bh+Bl), 3-term product.
// A: MxK (K-major), B: NxK (K-major). MODE: 0 store, 1 +=Cadd, 2 +=bias1+bias2
// ---------------------------------------------------------------------------
template <int MODE>
__global__ void __launch_bounds__(256, 2) gemm3x(
    const __nv_bfloat16* __restrict__ Ah, const __nv_bfloat16* __restrict__ Al,
    const __nv_bfloat16* __restrict__ Bh, const __nv_bfloat16* __restrict__ Bl,
    const float* __restrict__ Cadd, const float* __restrict__ bias1,
    const float* __restrict__ bias2, float* __restrict__ C,
    int K, int N, long sA, long sB, long sC)
{
    extern __shared__ char smem[];
    const uint32_t sb = smem_u32(smem);
    const int tid = threadIdx.x;
    const int lane = tid & 31, wid = tid >> 5;
    const int wm = wid & 3, wn = wid >> 2;
    const long z = blockIdx.z;
    Ah += z * sA; Al += z * sA; Bh += z * sB; Bl += z * sB; C += z * sC;
    const float* CaddZ = (MODE == 1) ? (Cadd + z * sC) : nullptr;
    const int bm = blockIdx.y * BM;
    const int bn = blockIdx.x * BN;

    float acc[2][8][4] = {};

    // loader lanes: 2 rows x 1 chunk per tile
    const int lr = tid >> 2;      // 0..63
    const int lc = tid & 3;       // 16B chunk within 64B row

    // ldmatrix lane geometry
    const int arow_b = wm * 32 + (lane & 15);                       // + mi*16
    const int brow_b = wn * 64 + (lane & 7) + ((lane & 16) ? 8 : 0); // + nt*16
    const int acs = (lane >> 4) << 4;       // A k-half byte sel: 0/16
    const int bcs = (lane & 8) ? 16 : 0;    // B k-half byte sel

    const int KT = K >> 5;

    // ---- stage loader ----
    auto load_stage = [&](int kt) {
        uint32_t base = sb + (uint32_t)(kt & 1) * STAGE_BYTES;
        int col = kt * BK + lc * 8;
#pragma unroll
        for (int i = 0; i < 2; i++) {
            int r = lr + i * 64;
            uint32_t off = sw64((uint32_t)(r * 64 + lc * 16));
            cp16(base + off,          Ah + (long)(bm + r) * K + col);
            cp16(base + 8192u + off,  Al + (long)(bm + r) * K + col);
            cp16(base + 16384u + off, Bh + (long)(bn + r) * K + col);
            cp16(base + 24576u + off, Bl + (long)(bn + r) * K + col);
        }
        asm volatile("cp.async.commit_group;" ::: "memory");
    };

    load_stage(0);

    for (int kt = 0; kt < KT; kt++) {
        if (kt + 1 < KT) {
            load_stage(kt + 1);
            asm volatile("cp.async.wait_group 1;" ::: "memory");
        } else {
            asm volatile("cp.async.wait_group 0;" ::: "memory");
        }
        __syncthreads();

        const uint32_t base = sb + (uint32_t)(kt & 1) * STAGE_BYTES;
#pragma unroll
        for (int kc = 0; kc < 2; kc++) {          // two k16 chunks in BK=32
            uint32_t ah[2][4], al[2][4];
#pragma unroll
            for (int mi = 0; mi < 2; mi++) {
                int row = arow_b + mi * 16;
                uint32_t addr = base + sw64((uint32_t)(row * 64 + kc * 32 + acs));
                ldm4(ah[mi], addr);
                ldm4(al[mi], addr + 8192u);
            }
#pragma unroll
            for (int nt = 0; nt < 4; nt++) {
                int row = brow_b + nt * 16;
                uint32_t addr = base + 16384u + sw64((uint32_t)(row * 64 + kc * 32 + bcs));
                uint32_t bh[4], bl[4];
                ldm4(bh, addr);
                ldm4(bl, addr + 8192u);
#pragma unroll
                for (int mi = 0; mi < 2; mi++) {
#pragma unroll
                    for (int hh = 0; hh < 2; hh++) {
                        int nj = nt * 2 + hh;
                        mma16816(acc[mi][nj], ah[mi], bh + 2 * hh);   // hi*hi
                        mma16816(acc[mi][nj], ah[mi], bl + 2 * hh);   // hi*lo
                        mma16816(acc[mi][nj], al[mi], bh + 2 * hh);   // lo*hi
                    }
                }
            }
        }
        __syncthreads();
    }

    // ---- epilogue ----
#pragma unroll
    for (int mi = 0; mi < 2; mi++) {
#pragma unroll
        for (int nj = 0; nj < 8; nj++) {
            int mrow = bm + wm * 32 + mi * 16 + (lane >> 2);
            int ncol = bn + wn * 64 + nj * 8 + (lane & 3) * 2;
            float2 v0 = make_float2(acc[mi][nj][0], acc[mi][nj][1]);
            float2 v1 = make_float2(acc[mi][nj][2], acc[mi][nj][3]);
            if (MODE == 1) {
                float2 a0 = *(const float2*)(CaddZ + (long)mrow * N + ncol);
                float2 a1 = *(const float2*)(CaddZ + (long)(mrow + 8) * N + ncol);
                v0.x += a0.x; v0.y += a0.y; v1.x += a1.x; v1.y += a1.y;
            } else if (MODE == 2) {
                float b0 = bias1[ncol] + bias2[ncol];
                float b1 = bias1[ncol + 1] + bias2[ncol + 1];
                v0.x += b0; v0.y += b1; v1.x += b0; v1.y += b1;
            }
            *(float2*)(C + (long)mrow * N + ncol) = v0;
            *(float2*)(C + (long)(mrow + 8) * N + ncol) = v1;
        }
    }
}

// ---------------------------------------------------------------------------
// decompose fp32 -> (bf16 hi, bf16 lo)
// ---------------------------------------------------------------------------
__global__ __launch_bounds__(256) void decomp(const float* __restrict__ x,
    __nv_bfloat16* __restrict__ hi, __nv_bfloat16* __restrict__ lo)
{
    long i = (long)blockIdx.x * 256 + threadIdx.x;
    float4 v = ((const float4*)x)[i];
    __nv_bfloat16 h0 = __float2bfloat16(v.x), h1 = __float2bfloat16(v.y);
    __nv_bfloat16 h2 = __float2bfloat16(v.z), h3 = __float2bfloat16(v.w);
    ((__nv_bfloat162*)hi)[2 * i]     = __halves2bfloat162(h0, h1);
    ((__nv_bfloat162*)hi)[2 * i + 1] = __halves2bfloat162(h2, h3);
    ((__nv_bfloat162*)lo)[2 * i]     = __halves2bfloat162(
        __float2bfloat16(v.x - __bfloat162float(h0)),
        __float2bfloat16(v.y - __bfloat162float(h1)));
    ((__nv_bfloat162*)lo)[2 * i + 1] = __halves2bfloat162(
        __float2bfloat16(v.z - __bfloat162float(h2)),
        __float2bfloat16(v.w - __bfloat162float(h3)));
}

// transpose sup [b][nk][e] -> supT [b][e][nk] with hi/lo decompose
__global__ void transdec(const float* __restrict__ sup,
    __nv_bfloat16* __restrict__ th, __nv_bfloat16* __restrict__ tl)
{
    __shared__ float t[32][33];
    int b = blockIdx.z;
    const float* S = sup + (long)b * NKDIM * EDIM;
    int e0 = blockIdx.x * 32, k0 = blockIdx.y * 32;
    int tx = threadIdx.x, ty = threadIdx.y;
#pragma unroll
    for (int i = 0; i < 4; i++)
        t[ty + 8 * i][tx] = S[(long)(k0 + ty + 8 * i) * EDIM + e0 + tx];
    __syncthreads();
    __nv_bfloat16* H = th + (long)b * EDIM * NKDIM;
    __nv_bfloat16* L = tl + (long)b * EDIM * NKDIM;
#pragma unroll
    for (int i = 0; i < 4; i++) {
        float v = t[tx][ty + 8 * i];
        __nv_bfloat16 h = __float2bfloat16(v);
        long o = (long)(e0 + ty + 8 * i) * NKDIM + k0 + tx;
        H[o] = h;
        L[o] = __float2bfloat16(v - __bfloat162float(h));
    }
}

// ---------------------------------------------------------------------------
// softmax over NK=1024 + bf16 hi/lo decompose of attn
// ---------------------------------------------------------------------------
__device__ __forceinline__ float warp_max(float v) {
#pragma unroll
    for (int o = 16; o; o >>= 1) v = fmaxf(v, __shfl_xor_sync(0xFFFFFFFFu, v, o));
    return v;
}
__device__ __forceinline__ float warp_sum(float v) {
#pragma unroll
    for (int o = 16; o; o >>= 1) v += __shfl_xor_sync(0xFFFFFFFFu, v, o);
    return v;
}

__global__ __launch_bounds__(256) void softmax_dec(const float* __restrict__ S,
    __nv_bfloat16* __restrict__ AH, __nv_bfloat16* __restrict__ AL)
{
    __shared__ float shm[8], shs[8];
    const long row = blockIdx.x;
    const float4* p = (const float4*)(S + row * (long)NKDIM);
    const int tid = threadIdx.x;

    float4 v = p[tid];
    float m = fmaxf(fmaxf(v.x, v.y), fmaxf(v.z, v.w));
    m = warp_max(m);
    if ((tid & 31) == 0) shm[tid >> 5] = m;
    __syncthreads();
    if (tid < 32) {
        float t = (tid < 8) ? shm[tid] : -3.402823466e38f;
        t = warp_max(t);
        if (tid == 0) shm[0] = t;
    }
    __syncthreads();
    m = shm[0];

    float ex = __expf(v.x - m), ey = __expf(v.y - m);
    float ez = __expf(v.z - m), ew = __expf(v.w - m);
    float s = (ex + ey) + (ez + ew);
    s = warp_sum(s);
    if ((tid & 31) == 0) shs[tid >> 5] = s;
    __syncthreads();
    if (tid < 32) {
        float t = (tid < 8) ? shs[tid] : 0.f;
        t = warp_sum(t);
        if (tid == 0) shs[0] = t;
    }
    __syncthreads();
    float inv = 1.f / shs[0];
    float a0 = ex * inv, a1 = ey * inv, a2 = ez * inv, a3 = ew * inv;

    __nv_bfloat16 h0 = __float2bfloat16(a0), h1 = __float2bfloat16(a1);
    __nv_bfloat16 h2 = __float2bfloat16(a2), h3 = __float2bfloat16(a3);
    __nv_bfloat162* ph = (__nv_bfloat162*)(AH + row * (long)NKDIM);
    __nv_bfloat162* pl = (__nv_bfloat162*)(AL + row * (long)NKDIM);
    ph[2 * tid]     = __halves2bfloat162(h0, h1);
    ph[2 * tid + 1] = __halves2bfloat162(h2, h3);
    pl[2 * tid]     = __halves2bfloat162(__float2bfloat16(a0 - __bfloat162float(h0)),
                                         __float2bfloat16(a1 - __bfloat162float(h1)));
    pl[2 * tid + 1] = __halves2bfloat162(__float2bfloat16(a2 - __bfloat162float(h2)),
                                         __float2bfloat16(a3 - __bfloat162float(h3)));
}

// ---------------------------------------------------------------------------
// LSTM pointwise
// ---------------------------------------------------------------------------
__global__ __launch_bounds__(256) void lstm_pw(const float* __restrict__ gates,
    const float* __restrict__ x, const float* __restrict__ r,
    float* __restrict__ c, __nv_bfloat16* __restrict__ hhi,
    __nv_bfloat16* __restrict__ hlo, float* __restrict__ outf, int last)
{
    long idx = (long)blockIdx.x * 256 + threadIdx.x;
    int m = (int)(idx >> 9), e = (int)(idx & 511);
    const float* g = gates + (long)m * G4;
    float gi = g[e], gf = g[512 + e], gg = g[1024 + e], go = g[1536 + e];
    float cn = sigf(gf) * c[idx] + sigf(gi) * tanhf(gg);
    float hn = sigf(go) * tanhf(cn) + x[idx] + r[idx];
    c[idx] = cn;
    __nv_bfloat16 hh = __float2bfloat16(hn);
    hhi[idx] = hh;
    hlo[idx] = __float2bfloat16(hn - __bfloat162float(hh));
    if (last) outf[idx] = hn;
}

__global__ void zero_hc(float* __restrict__ c, __nv_bfloat16* __restrict__ hhi,
                        __nv_bfloat16* __restrict__ hlo)
{
    long i = (long)blockIdx.x * 256 + threadIdx.x;
    c[i] = 0.f;
    __nv_bfloat16 z = __float2bfloat16(0.f);
    hhi[i] = z;
    hlo[i] = z;
}

// ---------------------------------------------------------------------------
extern "C" void kernel_launch(void* const* d_in, const int* in_sizes, int n_in,
                              void* d_out, int out_size)
{
    const float* targets = (const float*)d_in[0];
    const float* sup     = (const float*)d_in[1];
    const float* W_ih    = (const float*)d_in[2];
    const float* W_hh    = (const float*)d_in[3];
    const float* b_ih    = (const float*)d_in[4];
    const float* b_hh    = (const float*)d_in[5];
    float* out = (float*)d_out;

    float *xw, *gates, *scores, *r, *c;
    __nv_bfloat16 *h_hi, *h_lo, *tg_hi, *tg_lo, *wih_hi, *wih_lo, *whh_hi, *whh_lo;
    __nv_bfloat16 *sup_hi, *sup_lo, *supT_hi, *supT_lo, *attn_hi, *attn_lo;
    cudaGetSymbolAddress((void**)&xw, g_xw);
    cudaGetSymbolAddress((void**)&gates, g_gates);
    cudaGetSymbolAddress((void**)&scores, g_scores);
    cudaGetSymbolAddress((void**)&r, g_r);
    cudaGetSymbolAddress((void**)&c, g_c);
    cudaGetSymbolAddress((void**)&h_hi, g_h_hi);
    cudaGetSymbolAddress((void**)&h_lo, g_h_lo);
    cudaGetSymbolAddress((void**)&tg_hi, g_tg_hi);
    cudaGetSymbolAddress((void**)&tg_lo, g_tg_lo);
    cudaGetSymbolAddress((void**)&wih_hi, g_wih_hi);
    cudaGetSymbolAddress((void**)&wih_lo, g_wih_lo);
    cudaGetSymbolAddress((void**)&whh_hi, g_whh_hi);
    cudaGetSymbolAddress((void**)&whh_lo, g_whh_lo);
    cudaGetSymbolAddress((void**)&sup_hi, g_sup_hi);
    cudaGetSymbolAddress((void**)&sup_lo, g_sup_lo);
    cudaGetSymbolAddress((void**)&supT_hi, g_supT_hi);
    cudaGetSymbolAddress((void**)&supT_lo, g_supT_lo);
    cudaGetSymbolAddress((void**)&attn_hi, g_attn_hi);
    cudaGetSymbolAddress((void**)&attn_lo, g_attn_lo);

    cudaFuncSetAttribute(gemm3x<0>, cudaFuncAttributeMaxDynamicSharedMemorySize, DYN_SMEM);
    cudaFuncSetAttribute(gemm3x<1>, cudaFuncAttributeMaxDynamicSharedMemorySize, DYN_SMEM);
    cudaFuncSetAttribute(gemm3x<2>, cudaFuncAttributeMaxDynamicSharedMemorySize, DYN_SMEM);

    // ---- preamble (step-invariant) ----
    decomp<<<(long)BT * EDIM / 1024, 256>>>(targets, tg_hi, tg_lo);
    decomp<<<(long)G4 * EDIM / 1024, 256>>>(W_ih, wih_hi, wih_lo);
    decomp<<<(long)G4 * EDIM / 1024, 256>>>(W_hh, whh_hi, whh_lo);
    decomp<<<(long)NBAT * NKDIM * EDIM / 1024, 256>>>(sup, sup_hi, sup_lo);
    transdec<<<dim3(EDIM / 32, NKDIM / 32, NBAT), dim3(32, 8)>>>(sup, supT_hi, supT_lo);
    zero_hc<<<(long)BT * EDIM / 256, 256>>>(c, h_hi, h_lo);

    // xw = targets @ W_ih^T + b_ih + b_hh
    gemm3x<2><<<dim3(G4 / BN, BT / BM, 1), 256, DYN_SMEM>>>(
        tg_hi, tg_lo, wih_hi, wih_lo, nullptr, b_ih, b_hh, xw,
        EDIM, G4, 0, 0, 0);

    for (int s = 0; s < STEPS; s++) {
        // gates = xw + h @ W_hh^T
        gemm3x<1><<<dim3(G4 / BN, BT / BM, 1), 256, DYN_SMEM>>>(
            h_hi, h_lo, whh_hi, whh_lo, xw, nullptr, nullptr, gates,
            EDIM, G4, 0, 0, 0);

        // scores[b,t,nk] = h[b,t,:] . sup[b,nk,:]
        gemm3x<0><<<dim3(NKDIM / BN, 1, NBAT), 256, DYN_SMEM>>>(
            h_hi, h_lo, sup_hi, sup_lo, nullptr, nullptr, nullptr, scores,
            EDIM, NKDIM, (long)TQ * EDIM, (long)NKDIM * EDIM, (long)TQ * NKDIM);

        // attn = softmax(scores) -> bf16 hi/lo
        softmax_dec<<<BT, 256>>>(scores, attn_hi, attn_lo);

        // r[b,t,e] = attn[b,t,:] . supT[b,e,:]
        gemm3x<0><<<dim3(EDIM / BN, 1, NBAT), 256, DYN_SMEM>>>(
            attn_hi, attn_lo, supT_hi, supT_lo, nullptr, nullptr, nullptr, r,
            NKDIM, EDIM, (long)TQ * NKDIM, (long)EDIM * NKDIM, (long)TQ * EDIM);

        // pointwise update
        lstm_pw<<<(long)BT * EDIM / 256, 256>>>(
            gates, targets, r, c, h_hi, h_lo, out, (s == STEPS - 1) ? 1 : 0);
    }
}

// round 11
// speedup vs baseline: 3.0910x; 1.0342x over previous
#include <cuda_runtime.h>
#include <cuda_bf16.h>
#include <cstdint>
#include <math.h>

// ---------------- problem constants ----------------
#define BT    8192   // B*T
#define EDIM  512
#define G4    2048   // 4*E
#define NKDIM 1024   // N*K_SUP
#define NBAT  64
#define TQ    128
#define STEPS 10

// ---------------- GEMM tile config ----------------
#define BM 128
#define BN 128
#define BK 32
#define STAGE_BYTES 32768u   // Ah 8K + Al 8K + Bh 8K + Bl 8K
#define NSTAGE 3
#define DYN_SMEM    98304    // 3 stages

// ---------------- device scratch ----------------
__device__ float g_xw[(long)BT * G4];
__device__ float g_gates[(long)BT * G4];
__device__ float g_scores[(long)BT * NKDIM];
__device__ float g_r[(long)BT * EDIM];
__device__ float g_c[(long)BT * EDIM];
__device__ __nv_bfloat16 g_h_hi[(long)BT * EDIM];
__device__ __nv_bfloat16 g_h_lo[(long)BT * EDIM];
__device__ __nv_bfloat16 g_tg_hi[(long)BT * EDIM];
__device__ __nv_bfloat16 g_tg_lo[(long)BT * EDIM];
__device__ __nv_bfloat16 g_wih_hi[(long)G4 * EDIM];
__device__ __nv_bfloat16 g_wih_lo[(long)G4 * EDIM];
__device__ __nv_bfloat16 g_whh_hi[(long)G4 * EDIM];
__device__ __nv_bfloat16 g_whh_lo[(long)G4 * EDIM];
__device__ __nv_bfloat16 g_sup_hi[(long)NBAT * NKDIM * EDIM];
__device__ __nv_bfloat16 g_sup_lo[(long)NBAT * NKDIM * EDIM];
__device__ __nv_bfloat16 g_supT_hi[(long)NBAT * EDIM * NKDIM];
__device__ __nv_bfloat16 g_supT_lo[(long)NBAT * EDIM * NKDIM];
__device__ __nv_bfloat16 g_attn_hi[(long)BT * NKDIM];
__device__ __nv_bfloat16 g_attn_lo[(long)BT * NKDIM];

// ---------------- helpers ----------------
__device__ __forceinline__ uint32_t smem_u32(const void* p) {
    uint32_t a;
    asm("{ .reg .u64 t; cvta.to.shared.u64 t, %1; cvt.u32.u64 %0, t; }" : "=r"(a) : "l"(p));
    return a;
}
__device__ __forceinline__ void cp16(uint32_t dst, const void* src) {
    asm volatile("cp.async.cg.shared.global [%0], [%1], 16;" :: "r"(dst), "l"(src));
}
__device__ __forceinline__ uint32_t sw64(uint32_t x) { return x ^ ((x >> 3) & 0x30u); }

__device__ __forceinline__ void ldm4(uint32_t* r, uint32_t addr) {
    asm volatile("ldmatrix.sync.aligned.m8n8.x4.shared.b16 {%0,%1,%2,%3}, [%4];"
                 : "=r"(r[0]), "=r"(r[1]), "=r"(r[2]), "=r"(r[3]) : "r"(addr));
}
__device__ __forceinline__ void mma16816(float* c, const uint32_t* a, const uint32_t* b) {
    asm volatile(
        "mma.sync.aligned.m16n8k16.row.col.f32.bf16.bf16.f32 "
        "{%0,%1,%2,%3}, {%4,%5,%6,%7}, {%8,%9}, {%0,%1,%2,%3};"
        : "+f"(c[0]), "+f"(c[1]), "+f"(c[2]), "+f"(c[3])
        : "r"(a[0]), "r"(a[1]), "r"(a[2]), "r"(a[3]), "r"(b[0]), "r"(b[1]));
}

__device__ __forceinline__ float sigf(float x) { return 1.f / (1.f + __expf(-x)); }

// ---------------------------------------------------------------------------
// bf16x3 split GEMM (NT): C = A*B^T, 3-term hi/lo product. 3-stage pipeline.
// MODE: 0 store, 1 +=Cadd, 2 +=bias1+bias2
// ---------------------------------------------------------------------------
template <int MODE>
__global__ void __launch_bounds__(256, 2) gemm3x(
    const __nv_bfloat16* __restrict__ Ah, const __nv_bfloat16* __restrict__ Al,
    const __nv_bfloat16* __restrict__ Bh, const __nv_bfloat16* __restrict__ Bl,
    const float* __restrict__ Cadd, const float* __restrict__ bias1,
    const float* __restrict__ bias2, float* __restrict__ C,
    int K, int N, long sA, long sB, long sC)
{
    extern __shared__ char smem[];
    const uint32_t sb = smem_u32(smem);
    const int tid = threadIdx.x;
    const int lane = tid & 31, wid = tid >> 5;
    const int wm = wid & 3, wn = wid >> 2;
    const long z = blockIdx.z;
    Ah += z * sA; Al += z * sA; Bh += z * sB; Bl += z * sB; C += z * sC;
    const float* CaddZ = (MODE == 1) ? (Cadd + z * sC) : nullptr;
    const int bm = blockIdx.y * BM;
    const int bn = blockIdx.x * BN;

    float acc[2][8][4] = {};

    // loader lanes: 2 rows x 1 chunk per tile
    const int lr = tid >> 2;      // 0..63
    const int lc = tid & 3;       // 16B chunk within 64B row

    // ldmatrix lane geometry
    const int arow_b = wm * 32 + (lane & 15);                        // + mi*16
    const int brow_b = wn * 64 + (lane & 7) + ((lane & 16) ? 8 : 0); // + nt*16
    const int acs = (lane >> 4) << 4;       // A k-half byte sel: 0/16
    const int bcs = (lane & 8) ? 16 : 0;    // B k-half byte sel

    const int KT = K >> 5;   // BK = 32, KT >= 16 always here

    auto load_stage = [&](int kt) {
        uint32_t base = sb + (uint32_t)(kt % NSTAGE) * STAGE_BYTES;
        int col = kt * BK + lc * 8;
#pragma unroll
        for (int i = 0; i < 2; i++) {
            int r = lr + i * 64;
            uint32_t off = sw64((uint32_t)(r * 64 + lc * 16));
            cp16(base + off,          Ah + (long)(bm + r) * K + col);
            cp16(base + 8192u + off,  Al + (long)(bm + r) * K + col);
            cp16(base + 16384u + off, Bh + (long)(bn + r) * K + col);
            cp16(base + 24576u + off, Bl + (long)(bn + r) * K + col);
        }
        asm volatile("cp.async.commit_group;" ::: "memory");
    };

    load_stage(0);
    load_stage(1);

    for (int kt = 0; kt < KT; kt++) {
        if (kt + 2 < KT) {
            load_stage(kt + 2);   // overwrites slot of stage kt-1 (consumed, fenced)
            asm volatile("cp.async.wait_group 2;" ::: "memory");
        } else if (kt + 1 < KT) {
            asm volatile("cp.async.wait_group 1;" ::: "memory");
        } else {
            asm volatile("cp.async.wait_group 0;" ::: "memory");
        }
        __syncthreads();

        const uint32_t base = sb + (uint32_t)(kt % NSTAGE) * STAGE_BYTES;
#pragma unroll
        for (int kc = 0; kc < 2; kc++) {          // two k16 chunks in BK=32
            uint32_t ah[2][4], al[2][4];
#pragma unroll
            for (int mi = 0; mi < 2; mi++) {
                int row = arow_b + mi * 16;
                uint32_t addr = base + sw64((uint32_t)(row * 64 + kc * 32 + acs));
                ldm4(ah[mi], addr);
                ldm4(al[mi], addr + 8192u);
            }
#pragma unroll
            for (int nt = 0; nt < 4; nt++) {
                int row = brow_b + nt * 16;
                uint32_t addr = base + 16384u + sw64((uint32_t)(row * 64 + kc * 32 + bcs));
                uint32_t bh[4], bl[4];
                ldm4(bh, addr);
                ldm4(bl, addr + 8192u);
#pragma unroll
                for (int mi = 0; mi < 2; mi++) {
#pragma unroll
                    for (int hh = 0; hh < 2; hh++) {
                        int nj = nt * 2 + hh;
                        mma16816(acc[mi][nj], ah[mi], bh + 2 * hh);   // hi*hi
                        mma16816(acc[mi][nj], ah[mi], bl + 2 * hh);   // hi*lo
                        mma16816(acc[mi][nj], al[mi], bh + 2 * hh);   // lo*hi
                    }
                }
            }
        }
        __syncthreads();
    }

    // ---- epilogue ----
#pragma unroll
    for (int mi = 0; mi < 2; mi++) {
#pragma unroll
        for (int nj = 0; nj < 8; nj++) {
            int mrow = bm + wm * 32 + mi * 16 + (lane >> 2);
            int ncol = bn + wn * 64 + nj * 8 + (lane & 3) * 2;
            float2 v0 = make_float2(acc[mi][nj][0], acc[mi][nj][1]);
            float2 v1 = make_float2(acc[mi][nj][2], acc[mi][nj][3]);
            if (MODE == 1) {
                float2 a0 = *(const float2*)(CaddZ + (long)mrow * N + ncol);
                float2 a1 = *(const float2*)(CaddZ + (long)(mrow + 8) * N + ncol);
                v0.x += a0.x; v0.y += a0.y; v1.x += a1.x; v1.y += a1.y;
            } else if (MODE == 2) {
                float b0 = bias1[ncol] + bias2[ncol];
                float b1 = bias1[ncol + 1] + bias2[ncol + 1];
                v0.x += b0; v0.y += b1; v1.x += b0; v1.y += b1;
            }
            *(float2*)(C + (long)mrow * N + ncol) = v0;
            *(float2*)(C + (long)(mrow + 8) * N + ncol) = v1;
        }
    }
}

// ---------------------------------------------------------------------------
// decompose fp32 -> (bf16 hi, bf16 lo)
// ---------------------------------------------------------------------------
__global__ __launch_bounds__(256) void decomp(const float* __restrict__ x,
    __nv_bfloat16* __restrict__ hi, __nv_bfloat16* __restrict__ lo)
{
    long i = (long)blockIdx.x * 256 + threadIdx.x;
    float4 v = ((const float4*)x)[i];
    __nv_bfloat16 h0 = __float2bfloat16(v.x), h1 = __float2bfloat16(v.y);
    __nv_bfloat16 h2 = __float2bfloat16(v.z), h3 = __float2bfloat16(v.w);
    ((__nv_bfloat162*)hi)[2 * i]     = __halves2bfloat162(h0, h1);
    ((__nv_bfloat162*)hi)[2 * i + 1] = __halves2bfloat162(h2, h3);
    ((__nv_bfloat162*)lo)[2 * i]     = __halves2bfloat162(
        __float2bfloat16(v.x - __bfloat162float(h0)),
        __float2bfloat16(v.y - __bfloat162float(h1)));
    ((__nv_bfloat162*)lo)[2 * i + 1] = __halves2bfloat162(
        __float2bfloat16(v.z - __bfloat162float(h2)),
        __float2bfloat16(v.w - __bfloat162float(h3)));
}

// ---------------------------------------------------------------------------
// fused: sup -> sup_hi/lo (K-major) AND supT_hi/lo (transposed), 1 read pass
// ---------------------------------------------------------------------------
__global__ void prep_sup(const float* __restrict__ sup,
    __nv_bfloat16* __restrict__ sh, __nv_bfloat16* __restrict__ sl,
    __nv_bfloat16* __restrict__ th, __nv_bfloat16* __restrict__ tl)
{
    __shared__ float t[32][33];
    int b = blockIdx.z;
    const float* S = sup + (long)b * NKDIM * EDIM;
    int e0 = blockIdx.x * 32, k0 = blockIdx.y * 32;
    int tx = threadIdx.x, ty = threadIdx.y;
    __nv_bfloat16* SH = sh + (long)b * NKDIM * EDIM;
    __nv_bfloat16* SL = sl + (long)b * NKDIM * EDIM;
#pragma unroll
    for (int i = 0; i < 4; i++) {
        int kr = k0 + ty + 8 * i;
        float v = S[(long)kr * EDIM + e0 + tx];
        t[ty + 8 * i][tx] = v;
        __nv_bfloat16 h = __float2bfloat16(v);
        long o = (long)kr * EDIM + e0 + tx;
        SH[o] = h;
        SL[o] = __float2bfloat16(v - __bfloat162float(h));
    }
    __syncthreads();
    __nv_bfloat16* H = th + (long)b * EDIM * NKDIM;
    __nv_bfloat16* L = tl + (long)b * EDIM * NKDIM;
#pragma unroll
    for (int i = 0; i < 4; i++) {
        float v = t[tx][ty + 8 * i];
        __nv_bfloat16 h = __float2bfloat16(v);
        long o = (long)(e0 + ty + 8 * i) * NKDIM + k0 + tx;
        H[o] = h;
        L[o] = __float2bfloat16(v - __bfloat162float(h));
    }
}

// ---------------------------------------------------------------------------
// softmax over NK=1024 + bf16 hi/lo decompose of attn
// ---------------------------------------------------------------------------
__device__ __forceinline__ float warp_max(float v) {
#pragma unroll
    for (int o = 16; o; o >>= 1) v = fmaxf(v, __shfl_xor_sync(0xFFFFFFFFu, v, o));
    return v;
}
__device__ __forceinline__ float warp_sum(float v) {
#pragma unroll
    for (int o = 16; o; o >>= 1) v += __shfl_xor_sync(0xFFFFFFFFu, v, o);
    return v;
}

__global__ __launch_bounds__(256) void softmax_dec(const float* __restrict__ S,
    __nv_bfloat16* __restrict__ AH, __nv_bfloat16* __restrict__ AL)
{
    __shared__ float shm[8], shs[8];
    const long row = blockIdx.x;
    const float4* p = (const float4*)(S + row * (long)NKDIM);
    const int tid = threadIdx.x;

    float4 v = p[tid];
    float m = fmaxf(fmaxf(v.x, v.y), fmaxf(v.z, v.w));
    m = warp_max(m);
    if ((tid & 31) == 0) shm[tid >> 5] = m;
    __syncthreads();
    if (tid < 32) {
        float t = (tid < 8) ? shm[tid] : -3.402823466e38f;
        t = warp_max(t);
        if (tid == 0) shm[0] = t;
    }
    __syncthreads();
    m = shm[0];

    float ex = __expf(v.x - m), ey = __expf(v.y - m);
    float ez = __expf(v.z - m), ew = __expf(v.w - m);
    float s = (ex + ey) + (ez + ew);
    s = warp_sum(s);
    if ((tid & 31) == 0) shs[tid >> 5] = s;
    __syncthreads();
    if (tid < 32) {
        float t = (tid < 8) ? shs[tid] : 0.f;
        t = warp_sum(t);
        if (tid == 0) shs[0] = t;
    }
    __syncthreads();
    float inv = 1.f / shs[0];
    float a0 = ex * inv, a1 = ey * inv, a2 = ez * inv, a3 = ew * inv;

    __nv_bfloat16 h0 = __float2bfloat16(a0), h1 = __float2bfloat16(a1);
    __nv_bfloat16 h2 = __float2bfloat16(a2), h3 = __float2bfloat16(a3);
    __nv_bfloat162* ph = (__nv_bfloat162*)(AH + row * (long)NKDIM);
    __nv_bfloat162* pl = (__nv_bfloat162*)(AL + row * (long)NKDIM);
    ph[2 * tid]     = __halves2bfloat162(h0, h1);
    ph[2 * tid + 1] = __halves2bfloat162(h2, h3);
    pl[2 * tid]     = __halves2bfloat162(__float2bfloat16(a0 - __bfloat162float(h0)),
                                         __float2bfloat16(a1 - __bfloat162float(h1)));
    pl[2 * tid + 1] = __halves2bfloat162(__float2bfloat16(a2 - __bfloat162float(h2)),
                                         __float2bfloat16(a3 - __bfloat162float(h3)));
}

// ---------------------------------------------------------------------------
// LSTM pointwise, float4 vectorized (4 consecutive e of one row per thread)
// ---------------------------------------------------------------------------
__global__ __launch_bounds__(256) void lstm_pw(const float* __restrict__ gates,
    const float* __restrict__ x, const float* __restrict__ r,
    float* __restrict__ c, __nv_bfloat16* __restrict__ hhi,
    __nv_bfloat16* __restrict__ hlo, float* __restrict__ outf, int last)
{
    long i4 = (long)blockIdx.x * 256 + threadIdx.x;   // float4 index
    long base = i4 * 4;
    int m = (int)(base >> 9);
    int e = (int)(base & 511);
    const float* g = gates + (long)m * G4 + e;
    float4 gi = *(const float4*)(g);
    float4 gf = *(const float4*)(g + 512);
    float4 gg = *(const float4*)(g + 1024);
    float4 go = *(const float4*)(g + 1536);
    float4 cv = ((const float4*)c)[i4];
    float4 xv = ((const float4*)x)[i4];
    float4 rv = ((const float4*)r)[i4];

    float cn0 = sigf(gf.x) * cv.x + sigf(gi.x) * tanhf(gg.x);
    float cn1 = sigf(gf.y) * cv.y + sigf(gi.y) * tanhf(gg.y);
    float cn2 = sigf(gf.z) * cv.z + sigf(gi.z) * tanhf(gg.z);
    float cn3 = sigf(gf.w) * cv.w + sigf(gi.w) * tanhf(gg.w);
    float h0 = sigf(go.x) * tanhf(cn0) + xv.x + rv.x;
    float h1 = sigf(go.y) * tanhf(cn1) + xv.y + rv.y;
    float h2 = sigf(go.z) * tanhf(cn2) + xv.z + rv.z;
    float h3 = sigf(go.w) * tanhf(cn3) + xv.w + rv.w;

    ((float4*)c)[i4] = make_float4(cn0, cn1, cn2, cn3);
    __nv_bfloat16 b0 = __float2bfloat16(h0), b1 = __float2bfloat16(h1);
    __nv_bfloat16 b2 = __float2bfloat16(h2), b3 = __float2bfloat16(h3);
    ((__nv_bfloat162*)hhi)[2 * i4]     = __halves2bfloat162(b0, b1);
    ((__nv_bfloat162*)hhi)[2 * i4 + 1] = __halves2bfloat162(b2, b3);
    ((__nv_bfloat162*)hlo)[2 * i4]     = __halves2bfloat162(
        __float2bfloat16(h0 - __bfloat162float(b0)),
        __float2bfloat16(h1 - __bfloat162float(b1)));
    ((__nv_bfloat162*)hlo)[2 * i4 + 1] = __halves2bfloat162(
        __float2bfloat16(h2 - __bfloat162float(b2)),
        __float2bfloat16(h3 - __bfloat162float(b3)));
    if (last) ((float4*)outf)[i4] = make_float4(h0, h1, h2, h3);
}

__global__ void zero_hc(float* __restrict__ c, __nv_bfloat16* __restrict__ hhi,
                        __nv_bfloat16* __restrict__ hlo)
{
    long i = (long)blockIdx.x * 256 + threadIdx.x;
    c[i] = 0.f;
    __nv_bfloat16 z = __float2bfloat16(0.f);
    hhi[i] = z;
    hlo[i] = z;
}

// ---------------------------------------------------------------------------
extern "C" void kernel_launch(void* const* d_in, const int* in_sizes, int n_in,
                              void* d_out, int out_size)
{
    const float* targets = (const float*)d_in[0];
    const float* sup     = (const float*)d_in[1];
    const float* W_ih    = (const float*)d_in[2];
    const float* W_hh    = (const float*)d_in[3];
    const float* b_ih    = (const float*)d_in[4];
    const float* b_hh    = (const float*)d_in[5];
    float* out = (float*)d_out;

    float *xw, *gates, *scores, *r, *c;
    __nv_bfloat16 *h_hi, *h_lo, *tg_hi, *tg_lo, *wih_hi, *wih_lo, *whh_hi, *whh_lo;
    __nv_bfloat16 *sup_hi, *sup_lo, *supT_hi, *supT_lo, *attn_hi, *attn_lo;
    cudaGetSymbolAddress((void**)&xw, g_xw);
    cudaGetSymbolAddress((void**)&gates, g_gates);
    cudaGetSymbolAddress((void**)&scores, g_scores);
    cudaGetSymbolAddress((void**)&r, g_r);
    cudaGetSymbolAddress((void**)&c, g_c);
    cudaGetSymbolAddress((void**)&h_hi, g_h_hi);
    cudaGetSymbolAddress((void**)&h_lo, g_h_lo);
    cudaGetSymbolAddress((void**)&tg_hi, g_tg_hi);
    cudaGetSymbolAddress((void**)&tg_lo, g_tg_lo);
    cudaGetSymbolAddress((void**)&wih_hi, g_wih_hi);
    cudaGetSymbolAddress((void**)&wih_lo, g_wih_lo);
    cudaGetSymbolAddress((void**)&whh_hi, g_whh_hi);
    cudaGetSymbolAddress((void**)&whh_lo, g_whh_lo);
    cudaGetSymbolAddress((void**)&sup_hi, g_sup_hi);
    cudaGetSymbolAddress((void**)&sup_lo, g_sup_lo);
    cudaGetSymbolAddress((void**)&supT_hi, g_supT_hi);
    cudaGetSymbolAddress((void**)&supT_lo, g_supT_lo);
    cudaGetSymbolAddress((void**)&attn_hi, g_attn_hi);
    cudaGetSymbolAddress((void**)&attn_lo, g_attn_lo);

    cudaFuncSetAttribute(gemm3x<0>, cudaFuncAttributeMaxDynamicSharedMemorySize, DYN_SMEM);
    cudaFuncSetAttribute(gemm3x<1>, cudaFuncAttributeMaxDynamicSharedMemorySize, DYN_SMEM);
    cudaFuncSetAttribute(gemm3x<2>, cudaFuncAttributeMaxDynamicSharedMemorySize, DYN_SMEM);

    // ---- preamble (step-invariant) ----
    decomp<<<(long)BT * EDIM / 1024, 256>>>(targets, tg_hi, tg_lo);
    decomp<<<(long)G4 * EDIM / 1024, 256>>>(W_ih, wih_hi, wih_lo);
    decomp<<<(long)G4 * EDIM / 1024, 256>>>(W_hh, whh_hi, whh_lo);
    prep_sup<<<dim3(EDIM / 32, NKDIM / 32, NBAT), dim3(32, 8)>>>(
        sup, sup_hi, sup_lo, supT_hi, supT_lo);
    zero_hc<<<(long)BT * EDIM / 256, 256>>>(c, h_hi, h_lo);

    // xw = targets @ W_ih^T + b_ih + b_hh
    gemm3x<2><<<dim3(G4 / BN, BT / BM, 1), 256, DYN_SMEM>>>(
        tg_hi, tg_lo, wih_hi, wih_lo, nullptr, b_ih, b_hh, xw,
        EDIM, G4, 0, 0, 0);

    for (int s = 0; s < STEPS; s++) {
        // gates = xw + h @ W_hh^T
        gemm3x<1><<<dim3(G4 / BN, BT / BM, 1), 256, DYN_SMEM>>>(
            h_hi, h_lo, whh_hi, whh_lo, xw, nullptr, nullptr, gates,
            EDIM, G4, 0, 0, 0);

        // scores[b,t,nk] = h[b,t,:] . sup[b,nk,:]
        gemm3x<0><<<dim3(NKDIM / BN, 1, NBAT), 256, DYN_SMEM>>>(
            h_hi, h_lo, sup_hi, sup_lo, nullptr, nullptr, nullptr, scores,
            EDIM, NKDIM, (long)TQ * EDIM, (long)NKDIM * EDIM, (long)TQ * NKDIM);

        // attn = softmax(scores) -> bf16 hi/lo
        softmax_dec<<<BT, 256>>>(scores, attn_hi, attn_lo);

        // r[b,t,e] = attn[b,t,:] . supT[b,e,:]
        gemm3x<0><<<dim3(EDIM / BN, 1, NBAT), 256, DYN_SMEM>>>(
            attn_hi, attn_lo, supT_hi, supT_lo, nullptr, nullptr, nullptr, r,
            NKDIM, EDIM, (long)TQ * NKDIM, (long)EDIM * NKDIM, (long)TQ * EDIM);

        // pointwise update
        lstm_pw<<<(long)BT * EDIM / 1024, 256>>>(
            gates, targets, r, c, h_hi, h_lo, out, (s == STEPS - 1) ? 1 : 0);
    }
}